// round 2
// baseline (speedup 1.0000x reference)
#include <cuda_runtime.h>
#include <cstdint>

#define SA 20        // alphabet
#define HH 2
#define KK 2
#define NM 4         // H*K matrices
#define LL 512
#define BB 1024
#define NRATES 100000
#define NSWEEP 10

// persistent scratch (allocation-free rule: __device__ globals)
__device__ float g_U[NM][SA][SA];
__device__ float g_lam[NM][SA];
__device__ float g_sp[NM][SA];
__device__ float g_isp[NM][SA];

__device__ __forceinline__ float softplusf(float x) {
    return fmaxf(x, 0.f) + log1pf(expf(-fabsf(x)));
}

// ---------------- Kernel A: build Sm per (h,k) and Jacobi-diagonalize ----------------
__global__ void eig_kernel(const float* __restrict__ exch, const float* __restrict__ equil) {
    __shared__ float A[SA][SA + 1];
    __shared__ float Ut[SA][SA + 1];
    __shared__ float pvec[SA], spv[SA], ispv[SA], rowv[SA];
    __shared__ float csArr[SA / 2][2];
    __shared__ int   pqArr[SA / 2][2];
    __shared__ float inv_mue;

    const int m = blockIdx.x;     // m = h*KK + k
    const int t = threadIdx.x;

    // equilibrium softmax (serial, trivial)
    if (t == 0) {
        float mx = -1e30f;
        for (int s = 0; s < SA; s++) mx = fmaxf(mx, equil[m * SA + s]);
        float e[SA], sum = 0.f;
        for (int s = 0; s < SA; s++) { e[s] = expf(equil[m * SA + s] - mx); sum += e[s]; }
        float inv = 1.f / sum;
        for (int s = 0; s < SA; s++) {
            float ps = e[s] * inv;
            pvec[s] = ps;
            float sq = sqrtf(ps);
            spv[s] = sq;
            ispv[s] = 1.f / sq;
        }
    }
    __syncthreads();

    // Q_ij (pre-diagonal) = softplus(0.5*(Kij+Kji)) * (i!=j) * p_j
    for (int e = t; e < SA * SA; e += blockDim.x) {
        int i = e / SA, j = e % SA;
        float kij = exch[m * SA * SA + i * SA + j];
        float kji = exch[m * SA * SA + j * SA + i];
        float r = (i == j) ? 0.f : softplusf(0.5f * (kij + kji));
        A[i][j] = r * pvec[j];
    }
    __syncthreads();
    if (t < SA) { float s = 0.f; for (int j = 0; j < SA; j++) s += A[t][j]; rowv[t] = s; }
    __syncthreads();
    if (t == 0) {
        float mue = 0.f;
        for (int i = 0; i < SA; i++) mue += pvec[i] * rowv[i];
        inv_mue = 1.f / fmaxf(mue, 1e-16f);
    }
    __syncthreads();
    // Sm into Ut (temp), then symmetrize into A
    for (int e = t; e < SA * SA; e += blockDim.x) {
        int i = e / SA, j = e % SA;
        float q = (A[i][j] - ((i == j) ? rowv[i] : 0.f)) * inv_mue;
        Ut[i][j] = spv[i] * q * ispv[j];
    }
    __syncthreads();
    for (int e = t; e < SA * SA; e += blockDim.x) {
        int i = e / SA, j = e % SA;
        A[i][j] = 0.5f * (Ut[i][j] + Ut[j][i]);
    }
    __syncthreads();
    for (int e = t; e < SA * SA; e += blockDim.x) {
        int i = e / SA, j = e % SA;
        Ut[i][j] = (i == j) ? 1.f : 0.f;
    }

    // parallel Jacobi: 10 disjoint rotations per round, 19 rounds per sweep
    for (int sweep = 0; sweep < NSWEEP; sweep++) {
        for (int r = 0; r < SA - 1; r++) {
            __syncthreads();
            if (t < SA / 2) {
                int k = t;
                int posa = k, posb = SA - 1 - k;
                int P_ = (posa == 0) ? 0 : 1 + (posa - 1 + r) % (SA - 1);
                int Q_ = 1 + (posb - 1 + r) % (SA - 1);
                float app = A[P_][P_], aqq = A[Q_][Q_], apq = A[P_][Q_];
                float c = 1.f, s = 0.f;
                if (fabsf(apq) > 1e-13f) {
                    float theta = (aqq - app) / (2.f * apq);
                    float tt = copysignf(1.f, theta) / (fabsf(theta) + sqrtf(theta * theta + 1.f));
                    c = rsqrtf(tt * tt + 1.f);
                    s = tt * c;
                }
                pqArr[k][0] = P_; pqArr[k][1] = Q_;
                csArr[k][0] = c;  csArr[k][1] = s;
            }
            __syncthreads();
            if (t < (SA / 2) * SA) {                 // row phase: A = J^T A
                int k = t / SA, j = t % SA;
                int P_ = pqArr[k][0], Q_ = pqArr[k][1];
                float c = csArr[k][0], s = csArr[k][1];
                float ap = A[P_][j], aq = A[Q_][j];
                A[P_][j] = c * ap - s * aq;
                A[Q_][j] = s * ap + c * aq;
            }
            __syncthreads();
            if (t < (SA / 2) * SA) {                 // col phase: A = A J ; U = U J
                int k = t / SA, j = t % SA;
                int P_ = pqArr[k][0], Q_ = pqArr[k][1];
                float c = csArr[k][0], s = csArr[k][1];
                float ap = A[j][P_], aq = A[j][Q_];
                A[j][P_] = c * ap - s * aq;
                A[j][Q_] = s * ap + c * aq;
                float up = Ut[j][P_], uq = Ut[j][Q_];
                Ut[j][P_] = c * up - s * uq;
                Ut[j][Q_] = s * up + c * uq;
            }
        }
    }
    __syncthreads();
    for (int e = t; e < SA * SA; e += blockDim.x) {
        int i = e / SA, j = e % SA;
        g_U[m][i][j] = Ut[i][j];
    }
    if (t < SA) {
        g_lam[m][t] = A[t][t];
        g_sp[m][t]  = spv[t];
        g_isp[m][t] = ispv[t];
    }
}

// ---------------- Kernel B: per-b P reconstruction + one-hot gather ----------------
__global__ __launch_bounds__(512, 2)
void anc_kernel(const float* __restrict__ inputs, const int* __restrict__ ridx,
                const float* __restrict__ tauk, float* __restrict__ out) {
    // Pm is reinterpreted as float4: must be 16B-aligned. Row stride = 20 floats
    // = 80 bytes (multiple of 16), so aligning the base suffices.
    __shared__ __align__(16) float Pm[NM][SA][SA];   // Pm[h*KK+k][z][s]
    __shared__ __align__(16) float Us[NM][SA][SA];
    __shared__ __align__(16) float Vs[NM][SA][SA];
    __shared__ float w[NM][SA];
    __shared__ float sps[NM][SA], isps[NM][SA];
    __shared__ float tau[HH];

    const int b = blockIdx.x;
    const int t = threadIdx.x;

    if (t < HH) {
        int idx = ridx[b * HH + t];
        tau[t] = softplusf(tauk[t * NRATES + idx]);
    }
    __syncthreads();
    if (t < NM * SA) {
        int m = t / SA, s = t % SA;
        int h = m / KK;
        w[m][s]   = expf(tau[h] * g_lam[m][s]);
        sps[m][s] = g_sp[m][s];
        isps[m][s] = g_isp[m][s];
    }
    __syncthreads();
    for (int e = t; e < NM * SA * SA; e += blockDim.x) {
        int m = e / (SA * SA);
        int rs = e % (SA * SA);
        int j = rs / SA, s = rs % SA;
        float u = g_U[m][j][s];
        Us[m][j][s] = u;
        Vs[m][j][s] = u * w[m][s];
    }
    __syncthreads();
    for (int e = t; e < NM * SA * SA; e += blockDim.x) {
        int m = e / (SA * SA);
        int rs = e % (SA * SA);
        int i = rs / SA, j = rs % SA;
        float acc = 0.f;
#pragma unroll
        for (int s = 0; s < SA; s++) acc += Us[m][i][s] * Vs[m][j][s];
        Pm[m][i][j] = isps[m][i] * acc * sps[m][j];
    }
    __syncthreads();

    const int POS = LL * HH;   // 1024 positions per batch item
    for (int pos = t; pos < POS; pos += blockDim.x) {
        size_t ibase = ((size_t)b * POS + pos) * SA;      // *80 bytes -> 16B aligned
        const float4* ip = (const float4*)(inputs + ibase);
        float4 v0 = ip[0], v1 = ip[1], v2 = ip[2], v3 = ip[3], v4 = ip[4];
        float vals[SA] = { v0.x, v0.y, v0.z, v0.w,  v1.x, v1.y, v1.z, v1.w,
                           v2.x, v2.y, v2.z, v2.w,  v3.x, v3.y, v3.z, v3.w,
                           v4.x, v4.y, v4.z, v4.w };
        int z = 0; float best = vals[0];
#pragma unroll
        for (int i2 = 1; i2 < SA; i2++) {
            if (vals[i2] > best) { best = vals[i2]; z = i2; }
        }
        int h = pos & (HH - 1);
        int m0 = h * KK;
        size_t obase = ((size_t)b * POS + pos) * (KK * SA); // *160 bytes -> 16B aligned
        float4* op = (float4*)(out + obase);
        const float4* p0 = (const float4*)&Pm[m0][z][0];
        const float4* p1 = (const float4*)&Pm[m0 + 1][z][0];
        op[0] = p0[0]; op[1] = p0[1]; op[2] = p0[2]; op[3] = p0[3]; op[4] = p0[4];
        op[5] = p1[0]; op[6] = p1[1]; op[7] = p1[2]; op[8] = p1[3]; op[9] = p1[4];
    }
}

extern "C" void kernel_launch(void* const* d_in, const int* in_sizes, int n_in,
                              void* d_out, int out_size) {
    const float* inputs = (const float*)d_in[0];   // (B,L,H,20) f32
    const int*   ridx   = (const int*)d_in[1];     // (B,H) i32
    const float* tauk   = (const float*)d_in[2];   // (H,NUM_RATES) f32
    const float* exch   = (const float*)d_in[3];   // (H,K,20,20) f32
    const float* equil  = (const float*)d_in[4];   // (H,K,20) f32
    float* out = (float*)d_out;                    // (B,L,H,K,20) f32

    eig_kernel<<<NM, 256>>>(exch, equil);
    anc_kernel<<<BB, 512>>>(inputs, ridx, tauk, out);
}

// round 3
// speedup vs baseline: 1.1088x; 1.1088x over previous
#include <cuda_runtime.h>
#include <cstdint>

#define SA 20        // alphabet
#define HH 2
#define KK 2
#define NM 4         // H*K matrices
#define LL 512
#define BB 1024
#define NRATES 100000
#define NSWEEP 6
#define BPB 4        // blocks per batch item in anc kernel

// persistent scratch (allocation-free rule: __device__ globals)
__device__ float g_U[NM][SA][SA];
__device__ float g_lam[NM][SA];
__device__ float g_sp[NM][SA];
__device__ float g_isp[NM][SA];

__device__ __forceinline__ float softplusf(float x) {
    return fmaxf(x, 0.f) + log1pf(expf(-fabsf(x)));
}

// ---------------- Kernel A: build Sm per (h,k) and Jacobi-diagonalize ----------------
// Single-phase double-buffered parallel Jacobi: per round, 10 disjoint rotations.
// A' = J^T A J computed element-wise from the OLD buffer:
//   A'[i][j] = ci*(cj*A[i][j] + sj*A[i][pj]) + si*(cj*A[pi][j] + sj*A[pi][pj])
// where for a pair (P,Q): cc[P]=cc[Q]=c, ss[P]=-s, ss[Q]=+s, partner[P]=Q.
// Only 2 barriers per round, no intra-phase dependency chains.
__global__ __launch_bounds__(512, 1)
void eig_kernel(const float* __restrict__ exch, const float* __restrict__ equil) {
    __shared__ float A[2][SA][SA + 1];
    __shared__ float Ut[2][SA][SA + 1];
    __shared__ float cc[SA], ssg[SA];
    __shared__ int   part[SA];
    __shared__ float pvec[SA], spv[SA], ispv[SA], rowv[SA];
    __shared__ float inv_mue;

    const int m = blockIdx.x;     // m = h*KK + k
    const int t = threadIdx.x;

    // equilibrium softmax (serial, trivial)
    if (t == 0) {
        float mx = -1e30f;
        for (int s = 0; s < SA; s++) mx = fmaxf(mx, equil[m * SA + s]);
        float e[SA], sum = 0.f;
        for (int s = 0; s < SA; s++) { e[s] = expf(equil[m * SA + s] - mx); sum += e[s]; }
        float inv = 1.f / sum;
        for (int s = 0; s < SA; s++) {
            float ps = e[s] * inv;
            pvec[s] = ps;
            float sq = sqrtf(ps);
            spv[s] = sq;
            ispv[s] = 1.f / sq;
        }
    }
    __syncthreads();

    // Q_ij (pre-diagonal) = softplus(0.5*(Kij+Kji)) * (i!=j) * p_j   -> A[0]
    if (t < SA * SA) {
        int i = t / SA, j = t % SA;
        float kij = exch[m * SA * SA + i * SA + j];
        float kji = exch[m * SA * SA + j * SA + i];
        float r = (i == j) ? 0.f : softplusf(0.5f * (kij + kji));
        A[0][i][j] = r * pvec[j];
    }
    __syncthreads();
    if (t < SA) { float s = 0.f; for (int j = 0; j < SA; j++) s += A[0][t][j]; rowv[t] = s; }
    __syncthreads();
    if (t == 0) {
        float mue = 0.f;
        for (int i = 0; i < SA; i++) mue += pvec[i] * rowv[i];
        inv_mue = 1.f / fmaxf(mue, 1e-16f);
    }
    __syncthreads();
    // Sm into A[1] (temp)
    if (t < SA * SA) {
        int i = t / SA, j = t % SA;
        float q = (A[0][i][j] - ((i == j) ? rowv[i] : 0.f)) * inv_mue;
        A[1][i][j] = spv[i] * q * ispv[j];
    }
    __syncthreads();
    // symmetrize into A[0]; init U = I
    if (t < SA * SA) {
        int i = t / SA, j = t % SA;
        A[0][i][j] = 0.5f * (A[1][i][j] + A[1][j][i]);
        Ut[0][i][j] = (i == j) ? 1.f : 0.f;
    }

    int cur = 0;
    for (int round = 0; round < NSWEEP * (SA - 1); round++) {
        int r = round % (SA - 1);
        __syncthreads();
        if (t < SA / 2) {
            int k = t;
            int posa = k, posb = SA - 1 - k;
            int P_ = (posa == 0) ? 0 : 1 + (posa - 1 + r) % (SA - 1);
            int Q_ = 1 + (posb - 1 + r) % (SA - 1);
            float app = A[cur][P_][P_], aqq = A[cur][Q_][Q_], apq = A[cur][P_][Q_];
            float c = 1.f, s = 0.f;
            if (fabsf(apq) > 1e-13f) {
                float theta = (aqq - app) / (2.f * apq);
                float tt = copysignf(1.f, theta) / (fabsf(theta) + sqrtf(theta * theta + 1.f));
                c = rsqrtf(tt * tt + 1.f);
                s = tt * c;
            }
            cc[P_] = c; ssg[P_] = -s; part[P_] = Q_;
            cc[Q_] = c; ssg[Q_] =  s; part[Q_] = P_;
        }
        __syncthreads();
        if (t < SA * SA) {
            int i = t / SA, j = t % SA;
            int pi = part[i], pj = part[j];
            float ci = cc[i], si = ssg[i];
            float cj = cc[j], sj = ssg[j];
            float a00 = A[cur][i][j],  a01 = A[cur][i][pj];
            float a10 = A[cur][pi][j], a11 = A[cur][pi][pj];
            A[cur ^ 1][i][j] = ci * (cj * a00 + sj * a01) + si * (cj * a10 + sj * a11);
            float u0 = Ut[cur][i][j], u1 = Ut[cur][i][pj];
            Ut[cur ^ 1][i][j] = cj * u0 + sj * u1;
        }
        cur ^= 1;
    }
    __syncthreads();
    if (t < SA * SA) {
        int i = t / SA, j = t % SA;
        g_U[m][i][j] = Ut[cur][i][j];
    }
    if (t < SA) {
        g_lam[m][t] = A[cur][t][t];
        g_sp[m][t]  = spv[t];
        g_isp[m][t] = ispv[t];
    }
}

// ---------------- Kernel B: per-b P reconstruction + one-hot gather ----------------
// 4 blocks per batch item, 256 threads, 1 position per thread.
__global__ __launch_bounds__(256, 8)
void anc_kernel(const float* __restrict__ inputs, const int* __restrict__ ridx,
                const float* __restrict__ tauk, float* __restrict__ out) {
    __shared__ __align__(16) float Pm[NM][SA][SA];   // Pm[h*KK+k][z][s]
    __shared__ __align__(16) float Us[NM][SA][SA];
    __shared__ __align__(16) float Vs[NM][SA][SA];
    __shared__ float w[NM][SA];
    __shared__ float sps[NM][SA], isps[NM][SA];
    __shared__ float tau[HH];

    const int b = blockIdx.x / BPB;
    const int q = blockIdx.x % BPB;
    const int t = threadIdx.x;

    if (t < HH) {
        int idx = ridx[b * HH + t];
        tau[t] = softplusf(tauk[t * NRATES + idx]);
    }
    __syncthreads();
    if (t < NM * SA) {
        int m = t / SA, s = t % SA;
        int h = m / KK;
        w[m][s]    = expf(tau[h] * g_lam[m][s]);
        sps[m][s]  = g_sp[m][s];
        isps[m][s] = g_isp[m][s];
    }
    __syncthreads();
    for (int e = t; e < NM * SA * SA; e += blockDim.x) {
        int m = e / (SA * SA);
        int rs = e % (SA * SA);
        int j = rs / SA, s = rs % SA;
        float u = g_U[m][j][s];
        Us[m][j][s] = u;
        Vs[m][j][s] = u * w[m][s];
    }
    __syncthreads();
    for (int e = t; e < NM * SA * SA; e += blockDim.x) {
        int m = e / (SA * SA);
        int rs = e % (SA * SA);
        int i = rs / SA, j = rs % SA;
        float acc = 0.f;
#pragma unroll
        for (int s = 0; s < SA; s++) acc += Us[m][i][s] * Vs[m][j][s];
        Pm[m][i][j] = isps[m][i] * acc * sps[m][j];
    }
    __syncthreads();

    const int POS = LL * HH;            // 1024 positions per batch item
    const int pos = q * (POS / BPB) + t;  // exactly one position per thread

    size_t ibase = ((size_t)b * POS + pos) * SA;        // *80B -> 16B aligned
    const float4* ip = (const float4*)(inputs + ibase);
    float4 v0 = ip[0], v1 = ip[1], v2 = ip[2], v3 = ip[3], v4 = ip[4];
    float vals[SA] = { v0.x, v0.y, v0.z, v0.w,  v1.x, v1.y, v1.z, v1.w,
                       v2.x, v2.y, v2.z, v2.w,  v3.x, v3.y, v3.z, v3.w,
                       v4.x, v4.y, v4.z, v4.w };
    int z = 0; float best = vals[0];
#pragma unroll
    for (int i2 = 1; i2 < SA; i2++) {
        if (vals[i2] > best) { best = vals[i2]; z = i2; }
    }
    int h = pos & (HH - 1);
    int m0 = h * KK;
    size_t obase = ((size_t)b * POS + pos) * (KK * SA); // *160B -> 16B aligned
    float4* op = (float4*)(out + obase);
    const float4* p0 = (const float4*)&Pm[m0][z][0];
    const float4* p1 = (const float4*)&Pm[m0 + 1][z][0];
    op[0] = p0[0]; op[1] = p0[1]; op[2] = p0[2]; op[3] = p0[3]; op[4] = p0[4];
    op[5] = p1[0]; op[6] = p1[1]; op[7] = p1[2]; op[8] = p1[3]; op[9] = p1[4];
}

extern "C" void kernel_launch(void* const* d_in, const int* in_sizes, int n_in,
                              void* d_out, int out_size) {
    const float* inputs = (const float*)d_in[0];   // (B,L,H,20) f32
    const int*   ridx   = (const int*)d_in[1];     // (B,H) i32
    const float* tauk   = (const float*)d_in[2];   // (H,NUM_RATES) f32
    const float* exch   = (const float*)d_in[3];   // (H,K,20,20) f32
    const float* equil  = (const float*)d_in[4];   // (H,K,20) f32
    float* out = (float*)d_out;                    // (B,L,H,K,20) f32

    eig_kernel<<<NM, 512>>>(exch, equil);
    anc_kernel<<<BB * BPB, 256>>>(inputs, ridx, tauk, out);
}